// round 8
// baseline (speedup 1.0000x reference)
#include <cuda_runtime.h>

// ---------------------------------------------------------------------------
// GATv2 (H=2, EMB=64) + fused final linear, collapsed to scalar-per-edge form.
// R8: sign-grouped channels (segment-constant abs masks, no mask LDS),
//     launch_bounds(256,4) for 50% occupancy, merged setup kernel.
//
// Per-edge:  logit_h = 0.6*L_h + 0.4*sum_c att_hc*|z_hc|   (LeakyReLU split)
//            z_hc = s*Wl + t*Wr + a*We + b,  L_h = s*P_h + t*Q_h + a*R_h + B_h
// Per-node:  S_ih = sum_e alpha_eh * x[src_e]   (softmax without max-shift)
// Output:    out[i,:] = S_i0*A0 + S_i1*A1 + (CB + T0*D0 + T1*D1)
// ---------------------------------------------------------------------------

#define NODE_CAP 131072
#define EPT 4

typedef unsigned long long u64;

__device__ float4 g_accum[NODE_CAP];    // {den0, num0, den1, num1}
__device__ float2 g_degattr[NODE_CAP];  // {deg, attr_sum}

// --- edge weights, head-packed f32x2 (lo=head0, hi=head1), PERMUTED order
__device__ ulonglong2 g_eA[64];   // {wl2, wr2}
__device__ ulonglong2 g_eB[64];   // {we2, b2}
__device__ int g_off[4];          // sign-group boundaries (after groups 0..3)
__device__ u64 g_lin[4];          // P, Q, R, B head-packed

// --- node (self-loop) weights, head-packed, natural order
__device__ ulonglong2 g_nA[64];   // {wlr2, we2}
__device__ ulonglong2 g_nB[64];   // {b2, m2}
__device__ u64 g_nlpq, g_nlr, g_nlb;

// --- final linear vectors
__device__ __align__(16) float g_A0[128];
__device__ __align__(16) float g_A1[128];
__device__ __align__(16) float g_CB[128];
__device__ __align__(16) float g_D0[128];
__device__ __align__(16) float g_D1[128];
__device__ __align__(16) float g_Cv[128];   // CB + T0*D0 + T1*D1 (k_tgt)
__device__ int g_idx64;

// ---- f32x2 helpers ----
__device__ __forceinline__ u64 pack2(float lo, float hi) {
    u64 r;
    asm("mov.b64 %0, {%1, %2};" : "=l"(r) : "r"(__float_as_uint(lo)), "r"(__float_as_uint(hi)));
    return r;
}
__device__ __forceinline__ void unpack2(u64 v, float& lo, float& hi) {
    unsigned a, b;
    asm("mov.b64 {%0, %1}, %2;" : "=r"(a), "=r"(b) : "l"(v));
    lo = __uint_as_float(a); hi = __uint_as_float(b);
}
__device__ __forceinline__ u64 fma2(u64 a, u64 b, u64 c) {
    u64 d;
    asm("fma.rn.f32x2 %0, %1, %2, %3;" : "=l"(d) : "l"(a), "l"(b), "l"(c));
    return d;
}
__device__ __forceinline__ u64 add2(u64 a, u64 b) {
    u64 d;
    asm("add.rn.f32x2 %0, %1, %2;" : "=l"(d) : "l"(a), "l"(b));
    return d;
}
// per 32-bit half: (z & 0x7fffffff) | mask   (LOP3, immLut 0xEA)
__device__ __forceinline__ u64 abso2(u64 z, unsigned mlo, unsigned mhi) {
    unsigned lo, hi, rlo, rhi;
    asm("mov.b64 {%0, %1}, %2;" : "=r"(lo), "=r"(hi) : "l"(z));
    asm("lop3.b32 %0, %1, 0x7fffffff, %2, 0xEA;" : "=r"(rlo) : "r"(lo), "r"(mlo));
    asm("lop3.b32 %0, %1, 0x7fffffff, %2, 0xEA;" : "=r"(rhi) : "r"(hi), "r"(mhi));
    u64 r;
    asm("mov.b64 %0, {%1, %2};" : "=l"(r) : "r"(rlo), "r"(rhi));
    return r;
}
__device__ __forceinline__ float ex2f(float x) {
    float r;
    asm("ex2.approx.f32 %0, %1;" : "=f"(r) : "f"(x));
    return r;
}

// ---------------------------------------------------------------------------
// launch 0: merged setup.
//   block 0:        weight prep (edge permuted groups, node arrays, lin, dtype)
//   blocks 1..16:   final-linear vectors (warp per output row)
//   blocks 17+:     zero node accumulators
__global__ void __launch_bounds__(256) k_setup(
    const void* __restrict__ eidx, int n,
    const float* __restrict__ Wl, const float* __restrict__ bl,
    const float* __restrict__ Wr, const float* __restrict__ br,
    const float* __restrict__ We, const float* __restrict__ att,
    const float* __restrict__ bout, const float* __restrict__ Wfc,
    const float* __restrict__ bfc)
{
    const float LOG2E = 1.4426950408889634f;
    const float kap = 0.4f * LOG2E;
    const float lam = 0.6f * LOG2E;
    int bid = blockIdx.x;
    int tid = threadIdx.x;

    if (bid >= 17) {                 // zeroing
        int i = (bid - 17) * 256 + tid;
        if (i < n) {
            g_accum[i] = make_float4(0.f, 0.f, 0.f, 0.f);
            g_degattr[i] = make_float2(0.f, 0.f);
        }
        return;
    }
    if (bid >= 1) {                  // vecA: warp per output row j
        int lane = tid & 31;
        int j = (bid - 1) * 8 + (tid >> 5);
        const float* wrow = Wfc + j * 256;
        float a0 = 0.f, a1 = 0.f, cb = 0.f, d0 = 0.f, d1 = 0.f;
#pragma unroll
        for (int u = 0; u < 8; u++) {
            int idx = u * 32 + lane;
            float w = wrow[idx];
            if (u < 2) {
                a0 += Wl[idx] * w;
                cb += (bl[idx] + bout[idx]) * w;
            } else if (u < 4) {
                a1 += Wl[idx] * w;
                cb += (bl[idx] + bout[idx]) * w;
            } else if (u < 6) {
                int kk = idx - 128;
                cb += (bl[kk] + bout[kk]) * w;
                d0 += Wl[kk] * w;
            } else {
                int kk = idx - 128;
                cb += (bl[kk] + bout[kk]) * w;
                d1 += Wl[kk] * w;
            }
        }
#pragma unroll
        for (int off = 16; off > 0; off >>= 1) {
            a0 += __shfl_xor_sync(0xffffffffu, a0, off);
            a1 += __shfl_xor_sync(0xffffffffu, a1, off);
            cb += __shfl_xor_sync(0xffffffffu, cb, off);
            d0 += __shfl_xor_sync(0xffffffffu, d0, off);
            d1 += __shfl_xor_sync(0xffffffffu, d1, off);
        }
        if (lane == 0) {
            g_A0[j] = a0; g_A1[j] = a1; g_CB[j] = cb + bfc[j];
            g_D0[j] = d0; g_D1[j] = d1;
        }
        return;
    }

    // block 0: weight prep
    if (tid < 64) {   // node arrays (natural order, embedded masks)
        int c = tid;
        float a0 = att[c], a1 = att[64 + c];
        float k0 = kap * a0, k1 = kap * a1;
        float wl0 = k0 * Wl[c], wl1 = k1 * Wl[64 + c];
        float wr0 = k0 * Wr[c], wr1 = k1 * Wr[64 + c];
        float we0 = k0 * We[c], we1 = k1 * We[64 + c];
        float b0 = k0 * (bl[c] + br[c]), b1 = k1 * (bl[64 + c] + br[64 + c]);
        unsigned m0 = __float_as_uint(a0) & 0x80000000u;
        unsigned m1 = __float_as_uint(a1) & 0x80000000u;
        u64 m2 = ((u64)m1 << 32) | (u64)m0;
        ulonglong2 nA; nA.x = pack2(wl0 + wr0, wl1 + wr1); nA.y = pack2(we0, we1);
        ulonglong2 nB; nB.x = pack2(b0, b1); nB.y = m2;
        g_nA[c] = nA; g_nB[c] = nB;
    }
    if (tid == 0) {
        // sign-grouped permutation: group g = signbit(att0) | signbit(att1)<<1
        int cnt = 0;
        for (int g = 0; g < 4; g++) {
            for (int c = 0; c < 64; c++) {
                int gid = (att[c] < 0.f ? 1 : 0) | (att[64 + c] < 0.f ? 2 : 0);
                if (gid != g) continue;
                float a0 = att[c], a1 = att[64 + c];
                float k0 = kap * a0, k1 = kap * a1;
                ulonglong2 eA, eB;
                eA.x = pack2(k0 * Wl[c], k1 * Wl[64 + c]);
                eA.y = pack2(k0 * Wr[c], k1 * Wr[64 + c]);
                eB.x = pack2(k0 * We[c], k1 * We[64 + c]);
                eB.y = pack2(k0 * (bl[c] + br[c]), k1 * (bl[64 + c] + br[64 + c]));
                g_eA[cnt] = eA; g_eB[cnt] = eB;
                cnt++;
            }
            g_off[g] = cnt;
        }
        // linear parts
        float Ph[2], Qh[2], Rh[2], Bh[2];
        for (int h = 0; h < 2; h++) {
            float P = 0, Q = 0, R = 0, B = 0;
            for (int c = 0; c < 64; c++) {
                int j = h * 64 + c;
                float aA = att[j];
                P += aA * Wl[j]; Q += aA * Wr[j]; R += aA * We[j];
                B += aA * (bl[j] + br[j]);
            }
            Ph[h] = lam * P; Qh[h] = lam * Q; Rh[h] = lam * R; Bh[h] = lam * B;
        }
        g_lin[0] = pack2(Ph[0], Ph[1]);
        g_lin[1] = pack2(Qh[0], Qh[1]);
        g_lin[2] = pack2(Rh[0], Rh[1]);
        g_lin[3] = pack2(Bh[0], Bh[1]);
        g_nlpq = pack2(Ph[0] + Qh[0], Ph[1] + Qh[1]);
        g_nlr  = g_lin[2];
        g_nlb  = g_lin[3];
        // edge_index dtype detection (int64 values all < n)
        const u64* p = (const u64*)eidx;
        int is64 = 1;
        for (int k = 0; k < 16; k++)
            if (p[k] >= (u64)n) is64 = 0;
        g_idx64 = is64;
    }
}

// ---------------------------------------------------------------------------
// channel body: 4 edges, segment-constant masks
__device__ __forceinline__ void ch_body(
    ulonglong2 wA, ulonglong2 wB,
    const u64 (&s2)[EPT], const u64 (&t2)[EPT], const u64 (&a2)[EPT],
    u64 (&acc)[EPT], unsigned mlo, unsigned mhi)
{
#pragma unroll
    for (int k = 0; k < EPT; k++) {
        u64 z = fma2(a2[k], wB.x, wB.y);
        z = fma2(t2[k], wA.y, z);
        z = fma2(s2[k], wA.x, z);
        acc[k] = add2(acc[k], abso2(z, mlo, mhi));
    }
}

// launch 1: edge pass
__global__ void __launch_bounds__(256, 4) k_edges(
    const float* __restrict__ x, const void* __restrict__ eidx,
    const float* __restrict__ eattr, int E)
{
    __shared__ ulonglong2 s_eA[64], s_eB[64];
    int tid = threadIdx.x;
    if (tid < 64) { s_eA[tid] = g_eA[tid]; s_eB[tid] = g_eB[tid]; }
    __syncthreads();

    int base = (blockIdx.x * blockDim.x + tid) * EPT;
    if (base >= E) return;
    int idx64 = g_idx64;
    const long long* p64 = (const long long*)eidx;
    const int* p32 = (const int*)eidx;

    u64 s2[EPT], t2[EPT], a2[EPT], acc[EPT];
    int dsti[EPT];

#pragma unroll
    for (int k = 0; k < EPT; k++) {
        int e = base + k; if (e > E - 1) e = E - 1;
        int si, di;
        if (idx64) { si = (int)p64[e]; di = (int)p64[E + e]; }
        else       { si = p32[e];      di = p32[E + e]; }
        dsti[k] = di;
        float aa = eattr[e];
        float s = x[si], t = x[di];
        s2[k] = pack2(s, s); t2[k] = pack2(t, t); a2[k] = pack2(aa, aa);
        acc[k] = 0ull;
    }

    int o1 = g_off[0], o2 = g_off[1], o3 = g_off[2];
    int c = 0;
#pragma unroll 4
    for (; c < o1; c++) ch_body(s_eA[c], s_eB[c], s2, t2, a2, acc, 0u, 0u);
#pragma unroll 4
    for (; c < o2; c++) ch_body(s_eA[c], s_eB[c], s2, t2, a2, acc, 0x80000000u, 0u);
#pragma unroll 4
    for (; c < o3; c++) ch_body(s_eA[c], s_eB[c], s2, t2, a2, acc, 0u, 0x80000000u);
#pragma unroll 4
    for (; c < 64; c++) ch_body(s_eA[c], s_eB[c], s2, t2, a2, acc, 0x80000000u, 0x80000000u);

    u64 P = g_lin[0], Q = g_lin[1], R = g_lin[2], B = g_lin[3];
#pragma unroll
    for (int k = 0; k < EPT; k++) {
        if (base + k >= E) continue;
        u64 f2 = add2(acc[k], B);
        f2 = fma2(a2[k], R, f2);
        f2 = fma2(t2[k], Q, f2);
        f2 = fma2(s2[k], P, f2);
        float f0, f1; unpack2(f2, f0, f1);
        float e0 = ex2f(f0), e1 = ex2f(f1);
        float sv, av, dum;
        unpack2(s2[k], sv, dum);
        unpack2(a2[k], av, dum);
        atomicAdd(&g_degattr[dsti[k]], make_float2(1.0f, av));
        atomicAdd(&g_accum[dsti[k]], make_float4(e0, e0 * sv, e1, e1 * sv));
    }
}

// ---------------------------------------------------------------------------
// launch 2: S[target] + folded constant vector Cv (1 block, 128 threads)
__global__ void k_tgt(const float* __restrict__ x, const int* __restrict__ tgtp)
{
    __shared__ float2 sh_S;
    int tid = threadIdx.x;
    int tgt = tgtp[0];   // low 32 bits valid for int32/int64 (LE)
    if (tid < 32) {
        float s = x[tgt];
        float2 da = g_degattr[tgt];
        float am = da.y / fmaxf(da.x, 1.0f);
        u64 s2 = pack2(s, s), a2 = pack2(am, am);
        u64 acc = 0ull;
        for (int c = tid; c < 64; c += 32) {
            ulonglong2 A = g_nA[c], Bv = g_nB[c];
            u64 z = fma2(a2, A.y, Bv.x);
            z = fma2(s2, A.x, z);
            acc = add2(acc, abso2(z, (unsigned)Bv.y, (unsigned)(Bv.y >> 32)));
        }
        float h0, h1; unpack2(acc, h0, h1);
#pragma unroll
        for (int off = 16; off > 0; off >>= 1) {
            h0 += __shfl_xor_sync(0xffffffffu, h0, off);
            h1 += __shfl_xor_sync(0xffffffffu, h1, off);
        }
        u64 f = add2(pack2(h0, h1), fma2(s2, g_nlpq, fma2(a2, g_nlr, g_nlb)));
        float f0, f1; unpack2(f, f0, f1);
        float e0 = ex2f(f0), e1 = ex2f(f1);
        float4 ac = g_accum[tgt];
        if (tid == 0)
            sh_S = make_float2((ac.y + e0 * s) / (ac.x + e0),
                               (ac.w + e1 * s) / (ac.z + e1));
    }
    __syncthreads();
    float2 st = sh_S;
    if (tid < 128)
        g_Cv[tid] = fmaf(st.x, g_D0[tid], fmaf(st.y, g_D1[tid], g_CB[tid]));
}

// ---------------------------------------------------------------------------
// launch 3 (PROFILED): fused self-loop/softmax finalize + output write.
__global__ void __launch_bounds__(256) k_nodes_out(
    const float* __restrict__ x, int n, float* __restrict__ out)
{
    __shared__ ulonglong2 s_A[64], s_B[64];
    __shared__ float2 s_S[256];
    int tid = threadIdx.x;
    if (tid < 64) { s_A[tid] = g_nA[tid]; s_B[tid] = g_nB[tid]; }
    __syncthreads();

    int i = blockIdx.x * 256 + tid;
    int ii = (i < n) ? i : (n - 1);
    {
        float s = x[ii];
        float2 da = g_degattr[ii];
        float am = da.y / fmaxf(da.x, 1.0f);
        u64 s2 = pack2(s, s), a2 = pack2(am, am);
        u64 accE = 0ull, accO = 0ull;
#pragma unroll 4
        for (int c = 0; c < 64; c += 2) {
            ulonglong2 A0 = s_A[c],     B0 = s_B[c];
            ulonglong2 A1 = s_A[c + 1], B1 = s_B[c + 1];
            u64 z0 = fma2(a2, A0.y, B0.x); z0 = fma2(s2, A0.x, z0);
            u64 z1 = fma2(a2, A1.y, B1.x); z1 = fma2(s2, A1.x, z1);
            accE = add2(accE, abso2(z0, (unsigned)B0.y, (unsigned)(B0.y >> 32)));
            accO = add2(accO, abso2(z1, (unsigned)B1.y, (unsigned)(B1.y >> 32)));
        }
        u64 f = add2(add2(accE, accO), fma2(s2, g_nlpq, fma2(a2, g_nlr, g_nlb)));
        float f0, f1; unpack2(f, f0, f1);
        float e0 = ex2f(f0), e1 = ex2f(f1);
        float4 ac = g_accum[ii];
        s_S[tid] = make_float2((ac.y + e0 * s) / (ac.x + e0),
                               (ac.w + e1 * s) / (ac.z + e1));
    }
    __syncthreads();

    int lane = tid & 31, w = tid >> 5;
    float4 A0v = ((const float4*)g_A0)[lane];
    float4 A1v = ((const float4*)g_A1)[lane];
    float4 Cv  = ((const float4*)g_Cv)[lane];
    int base = blockIdx.x * 256 + w * 32;
    float4* o4 = (float4*)out;
#pragma unroll 4
    for (int j = 0; j < 32; j++) {
        int node = base + j;
        if (node >= n) break;
        float2 sS = s_S[w * 32 + j];
        float4 o;
        o.x = fmaf(sS.x, A0v.x, fmaf(sS.y, A1v.x, Cv.x));
        o.y = fmaf(sS.x, A0v.y, fmaf(sS.y, A1v.y, Cv.y));
        o.z = fmaf(sS.x, A0v.z, fmaf(sS.y, A1v.z, Cv.z));
        o.w = fmaf(sS.x, A0v.w, fmaf(sS.y, A1v.w, Cv.w));
        o4[(long long)node * 32 + lane] = o;
    }
}

// ---------------------------------------------------------------------------
extern "C" void kernel_launch(void* const* d_in, const int* in_sizes, int n_in,
                              void* d_out, int out_size)
{
    const float* x     = (const float*)d_in[0];
    const void*  eidx  = d_in[1];
    const float* eattr = (const float*)d_in[2];
    const int*   tgtp  = (const int*)d_in[3];
    const float* Wl    = (const float*)d_in[4];
    const float* bl    = (const float*)d_in[5];
    const float* Wr    = (const float*)d_in[6];
    const float* br    = (const float*)d_in[7];
    const float* We    = (const float*)d_in[8];
    const float* att   = (const float*)d_in[9];
    const float* bout  = (const float*)d_in[10];
    const float* Wfc   = (const float*)d_in[11];
    const float* bfc   = (const float*)d_in[12];

    int n = in_sizes[0];   // N nodes (x is [N,1])
    int E = in_sizes[2];   // edges (edge_attr is [E,1])
    float* out = (float*)d_out;

    int nblk = (n + 255) / 256;
    k_setup<<<nblk + 17, 256>>>(eidx, n, Wl, bl, Wr, br, We, att,
                                bout, Wfc, bfc);                 // idx 0
    int ethreads = (E + EPT - 1) / EPT;
    k_edges<<<(ethreads + 255) / 256, 256>>>(x, eidx, eattr, E); // idx 1
    k_tgt<<<1, 128>>>(x, tgtp);                                  // idx 2
    k_nodes_out<<<nblk, 256>>>(x, n, out);                       // idx 3 (profiled)
}

// round 10
// speedup vs baseline: 1.0469x; 1.0469x over previous
#include <cuda_runtime.h>

// ---------------------------------------------------------------------------
// GATv2 (H=2, EMB=64) + fused final linear, collapsed to scalar-per-edge form.
// R10: R9 with the k_nodes_out output-stride bug fixed (node*32, not node*16).
//      Edge kernel: EPT=2 + launch_bounds(256,4) occupancy experiment.
//
// Per-edge:  logit_h = 0.6*L_h + 0.4*sum_c att_hc*|z_hc|   (LeakyReLU split)
//            z_hc = s*Wl + t*Wr + a*We + b,  L_h = s*P_h + t*Q_h + a*R_h + B_h
// Per-node:  S_ih = sum_e alpha_eh * x[src_e]   (softmax without max-shift)
// Output:    out[i,:] = S_i0*A0 + S_i1*A1 + (CB + T0*D0 + T1*D1)
// ---------------------------------------------------------------------------

#define NODE_CAP 131072
#define EPT 2

typedef unsigned long long u64;

__device__ float4 g_accum[NODE_CAP];    // {den0, num0, den1, num1}
__device__ float2 g_degattr[NODE_CAP];  // {deg, attr_sum}

// --- edge weights, head-packed f32x2 (lo=head0, hi=head1), natural order
__device__ ulonglong2 g_eA[64];   // {wl2, wr2}
__device__ ulonglong2 g_eB[64];   // {we2, b2}
__device__ u64 g_em[64];          // per-half sign masks of att
__device__ u64 g_lin[4];          // P, Q, R, B head-packed

// --- node (self-loop) weights, head-packed, natural order
__device__ ulonglong2 g_nA[64];   // {wlr2, we2}
__device__ ulonglong2 g_nB[64];   // {b2, m2}
__device__ u64 g_nlpq, g_nlr, g_nlb;

// --- final linear vectors
__device__ __align__(16) float g_A0[128];
__device__ __align__(16) float g_A1[128];
__device__ __align__(16) float g_CB[128];
__device__ __align__(16) float g_D0[128];
__device__ __align__(16) float g_D1[128];
__device__ __align__(16) float g_Cv[128];   // CB + T0*D0 + T1*D1 (k_tgt)
__device__ int g_idx64;

// ---- f32x2 helpers ----
__device__ __forceinline__ u64 pack2(float lo, float hi) {
    u64 r;
    asm("mov.b64 %0, {%1, %2};" : "=l"(r) : "r"(__float_as_uint(lo)), "r"(__float_as_uint(hi)));
    return r;
}
__device__ __forceinline__ void unpack2(u64 v, float& lo, float& hi) {
    unsigned a, b;
    asm("mov.b64 {%0, %1}, %2;" : "=r"(a), "=r"(b) : "l"(v));
    lo = __uint_as_float(a); hi = __uint_as_float(b);
}
__device__ __forceinline__ u64 fma2(u64 a, u64 b, u64 c) {
    u64 d;
    asm("fma.rn.f32x2 %0, %1, %2, %3;" : "=l"(d) : "l"(a), "l"(b), "l"(c));
    return d;
}
__device__ __forceinline__ u64 add2(u64 a, u64 b) {
    u64 d;
    asm("add.rn.f32x2 %0, %1, %2;" : "=l"(d) : "l"(a), "l"(b));
    return d;
}
// per 32-bit half: (z & 0x7fffffff) | mask   (LOP3, immLut 0xEA)
__device__ __forceinline__ u64 abso2(u64 z, unsigned mlo, unsigned mhi) {
    unsigned lo, hi, rlo, rhi;
    asm("mov.b64 {%0, %1}, %2;" : "=r"(lo), "=r"(hi) : "l"(z));
    asm("lop3.b32 %0, %1, 0x7fffffff, %2, 0xEA;" : "=r"(rlo) : "r"(lo), "r"(mlo));
    asm("lop3.b32 %0, %1, 0x7fffffff, %2, 0xEA;" : "=r"(rhi) : "r"(hi), "r"(mhi));
    u64 r;
    asm("mov.b64 %0, {%1, %2};" : "=l"(r) : "r"(rlo), "r"(rhi));
    return r;
}
__device__ __forceinline__ float ex2f(float x) {
    float r;
    asm("ex2.approx.f32 %0, %1;" : "=f"(r) : "f"(x));
    return r;
}

// ---------------------------------------------------------------------------
// launch 0: zero accumulators
__global__ void __launch_bounds__(256) k_zero(int n)
{
    int i = blockIdx.x * blockDim.x + threadIdx.x;
    if (i < n) {
        g_accum[i] = make_float4(0.f, 0.f, 0.f, 0.f);
        g_degattr[i] = make_float2(0.f, 0.f);
    }
}

// ---------------------------------------------------------------------------
// launch 1: weight prep (1 block, 128 threads)
__global__ void k_wprep(const void* __restrict__ eidx, int n,
                        const float* __restrict__ Wl, const float* __restrict__ bl,
                        const float* __restrict__ Wr, const float* __restrict__ br,
                        const float* __restrict__ We, const float* __restrict__ att)
{
    const float LOG2E = 1.4426950408889634f;
    const float kap = 0.4f * LOG2E;
    const float lam = 0.6f * LOG2E;
    int tid = threadIdx.x;
    if (tid < 64) {
        int c = tid;
        float a0 = att[c], a1 = att[64 + c];
        float k0 = kap * a0, k1 = kap * a1;
        float wl0 = k0 * Wl[c], wl1 = k1 * Wl[64 + c];
        float wr0 = k0 * Wr[c], wr1 = k1 * Wr[64 + c];
        float we0 = k0 * We[c], we1 = k1 * We[64 + c];
        float b0 = k0 * (bl[c] + br[c]), b1 = k1 * (bl[64 + c] + br[64 + c]);
        unsigned m0 = __float_as_uint(a0) & 0x80000000u;
        unsigned m1 = __float_as_uint(a1) & 0x80000000u;
        u64 m2 = ((u64)m1 << 32) | (u64)m0;
        ulonglong2 eA; eA.x = pack2(wl0, wl1); eA.y = pack2(wr0, wr1);
        ulonglong2 eB; eB.x = pack2(we0, we1); eB.y = pack2(b0, b1);
        g_eA[c] = eA; g_eB[c] = eB; g_em[c] = m2;
        ulonglong2 nA; nA.x = pack2(wl0 + wr0, wl1 + wr1); nA.y = eB.x;
        ulonglong2 nB; nB.x = eB.y; nB.y = m2;
        g_nA[c] = nA; g_nB[c] = nB;
    }
    if (tid == 0) {
        float Ph[2], Qh[2], Rh[2], Bh[2];
        for (int h = 0; h < 2; h++) {
            float P = 0, Q = 0, R = 0, B = 0;
            for (int c = 0; c < 64; c++) {
                int j = h * 64 + c;
                float aA = att[j];
                P += aA * Wl[j]; Q += aA * Wr[j]; R += aA * We[j];
                B += aA * (bl[j] + br[j]);
            }
            Ph[h] = lam * P; Qh[h] = lam * Q; Rh[h] = lam * R; Bh[h] = lam * B;
        }
        g_lin[0] = pack2(Ph[0], Ph[1]);
        g_lin[1] = pack2(Qh[0], Qh[1]);
        g_lin[2] = pack2(Rh[0], Rh[1]);
        g_lin[3] = pack2(Bh[0], Bh[1]);
        g_nlpq = pack2(Ph[0] + Qh[0], Ph[1] + Qh[1]);
        g_nlr  = g_lin[2];
        g_nlb  = g_lin[3];
        // edge_index dtype detection (int64 values all < n)
        const u64* p = (const u64*)eidx;
        int is64 = 1;
        for (int k = 0; k < 16; k++)
            if (p[k] >= (u64)n) is64 = 0;
        g_idx64 = is64;
    }
}

// ---------------------------------------------------------------------------
// launch 2: final-linear vectors (weights-only). Warp per output row.
__global__ void __launch_bounds__(256) k_vecA(
    const float* __restrict__ Wl, const float* __restrict__ bl,
    const float* __restrict__ bout, const float* __restrict__ Wfc,
    const float* __restrict__ bfc)
{
    int lane = threadIdx.x & 31;
    int j = (blockIdx.x * blockDim.x + threadIdx.x) >> 5;
    if (j >= 128) return;
    const float* wrow = Wfc + j * 256;

    float a0 = 0.f, a1 = 0.f, cb = 0.f, d0 = 0.f, d1 = 0.f;
#pragma unroll
    for (int u = 0; u < 8; u++) {
        int idx = u * 32 + lane;
        float w = wrow[idx];
        if (u < 2) {
            a0 += Wl[idx] * w;
            cb += (bl[idx] + bout[idx]) * w;
        } else if (u < 4) {
            a1 += Wl[idx] * w;
            cb += (bl[idx] + bout[idx]) * w;
        } else if (u < 6) {
            int kk = idx - 128;
            cb += (bl[kk] + bout[kk]) * w;
            d0 += Wl[kk] * w;
        } else {
            int kk = idx - 128;
            cb += (bl[kk] + bout[kk]) * w;
            d1 += Wl[kk] * w;
        }
    }
#pragma unroll
    for (int off = 16; off > 0; off >>= 1) {
        a0 += __shfl_xor_sync(0xffffffffu, a0, off);
        a1 += __shfl_xor_sync(0xffffffffu, a1, off);
        cb += __shfl_xor_sync(0xffffffffu, cb, off);
        d0 += __shfl_xor_sync(0xffffffffu, d0, off);
        d1 += __shfl_xor_sync(0xffffffffu, d1, off);
    }
    if (lane == 0) {
        g_A0[j] = a0; g_A1[j] = a1; g_CB[j] = cb + bfc[j];
        g_D0[j] = d0; g_D1[j] = d1;
    }
}

// ---------------------------------------------------------------------------
// launch 3 (PROFILED): edge pass.  EPT=2, forced 4 CTAs/SM.
__global__ void __launch_bounds__(256, 4) k_edges(
    const float* __restrict__ x, const void* __restrict__ eidx,
    const float* __restrict__ eattr, int E)
{
    __shared__ ulonglong2 s_eA[64], s_eB[64];
    __shared__ u64 s_m[64];
    int tid = threadIdx.x;
    if (tid < 64) { s_eA[tid] = g_eA[tid]; s_eB[tid] = g_eB[tid]; s_m[tid] = g_em[tid]; }
    __syncthreads();

    int base = (blockIdx.x * blockDim.x + tid) * EPT;
    if (base >= E) return;
    int idx64 = g_idx64;
    const long long* p64 = (const long long*)eidx;
    const int* p32 = (const int*)eidx;

    u64 s2[EPT], t2[EPT], a2[EPT], acc[EPT];
    int dsti[EPT];

#pragma unroll
    for (int k = 0; k < EPT; k++) {
        int e = base + k; if (e > E - 1) e = E - 1;
        int si, di;
        if (idx64) { si = (int)p64[e]; di = (int)p64[E + e]; }
        else       { si = p32[e];      di = p32[E + e]; }
        dsti[k] = di;
        float aa = eattr[e];
        float s = x[si], t = x[di];
        s2[k] = pack2(s, s); t2[k] = pack2(t, t); a2[k] = pack2(aa, aa);
        acc[k] = 0ull;
    }

#pragma unroll 8
    for (int c = 0; c < 64; c++) {
        ulonglong2 wA = s_eA[c];   // {wl, wr}
        ulonglong2 wB = s_eB[c];   // {we, b}
        u64 mm = s_m[c];
        unsigned mlo = (unsigned)mm, mhi = (unsigned)(mm >> 32);
#pragma unroll
        for (int k = 0; k < EPT; k++) {
            u64 z = fma2(a2[k], wB.x, wB.y);
            z = fma2(t2[k], wA.y, z);
            z = fma2(s2[k], wA.x, z);
            acc[k] = add2(acc[k], abso2(z, mlo, mhi));
        }
    }

    u64 P = g_lin[0], Q = g_lin[1], R = g_lin[2], B = g_lin[3];
#pragma unroll
    for (int k = 0; k < EPT; k++) {
        if (base + k >= E) continue;
        u64 f2 = add2(acc[k], B);
        f2 = fma2(a2[k], R, f2);
        f2 = fma2(t2[k], Q, f2);
        f2 = fma2(s2[k], P, f2);
        float f0, f1; unpack2(f2, f0, f1);
        float e0 = ex2f(f0), e1 = ex2f(f1);
        float sv, av, dum;
        unpack2(s2[k], sv, dum);
        unpack2(a2[k], av, dum);
        atomicAdd(&g_degattr[dsti[k]], make_float2(1.0f, av));
        atomicAdd(&g_accum[dsti[k]], make_float4(e0, e0 * sv, e1, e1 * sv));
    }
}

// ---------------------------------------------------------------------------
// launch 4: S[target] + folded constant vector Cv (1 block, 128 threads)
__global__ void k_tgt(const float* __restrict__ x, const int* __restrict__ tgtp)
{
    __shared__ float2 sh_S;
    int tid = threadIdx.x;
    int tgt = tgtp[0];   // low 32 bits valid for int32/int64 (LE)
    if (tid < 32) {
        float s = x[tgt];
        float2 da = g_degattr[tgt];
        float am = da.y / fmaxf(da.x, 1.0f);
        u64 s2 = pack2(s, s), a2 = pack2(am, am);
        u64 acc = 0ull;
        for (int c = tid; c < 64; c += 32) {
            ulonglong2 A = g_nA[c], Bv = g_nB[c];
            u64 z = fma2(a2, A.y, Bv.x);
            z = fma2(s2, A.x, z);
            acc = add2(acc, abso2(z, (unsigned)Bv.y, (unsigned)(Bv.y >> 32)));
        }
        float h0, h1; unpack2(acc, h0, h1);
#pragma unroll
        for (int off = 16; off > 0; off >>= 1) {
            h0 += __shfl_xor_sync(0xffffffffu, h0, off);
            h1 += __shfl_xor_sync(0xffffffffu, h1, off);
        }
        u64 f = add2(pack2(h0, h1), fma2(s2, g_nlpq, fma2(a2, g_nlr, g_nlb)));
        float f0, f1; unpack2(f, f0, f1);
        float e0 = ex2f(f0), e1 = ex2f(f1);
        float4 ac = g_accum[tgt];
        if (tid == 0)
            sh_S = make_float2((ac.y + e0 * s) / (ac.x + e0),
                               (ac.w + e1 * s) / (ac.z + e1));
    }
    __syncthreads();
    float2 st = sh_S;
    if (tid < 128)
        g_Cv[tid] = fmaf(st.x, g_D0[tid], fmaf(st.y, g_D1[tid], g_CB[tid]));
}

// ---------------------------------------------------------------------------
// launch 5: fused self-loop/softmax finalize + output write (f32x2 phase 2).
__global__ void __launch_bounds__(256) k_nodes_out(
    const float* __restrict__ x, int n, float* __restrict__ out)
{
    __shared__ ulonglong2 s_A[64], s_B[64];
    __shared__ float2 s_S[256];
    int tid = threadIdx.x;
    if (tid < 64) { s_A[tid] = g_nA[tid]; s_B[tid] = g_nB[tid]; }
    __syncthreads();

    int i = blockIdx.x * 256 + tid;
    int ii = (i < n) ? i : (n - 1);
    {
        float s = x[ii];
        float2 da = g_degattr[ii];
        float am = da.y / fmaxf(da.x, 1.0f);
        u64 s2 = pack2(s, s), a2 = pack2(am, am);
        u64 acc0 = 0ull, acc1 = 0ull, acc2 = 0ull, acc3 = 0ull;
#pragma unroll 2
        for (int c = 0; c < 64; c += 4) {
            ulonglong2 A0 = s_A[c],     B0 = s_B[c];
            ulonglong2 A1 = s_A[c + 1], B1 = s_B[c + 1];
            ulonglong2 A2 = s_A[c + 2], B2 = s_B[c + 2];
            ulonglong2 A3 = s_A[c + 3], B3 = s_B[c + 3];
            u64 z0 = fma2(s2, A0.x, fma2(a2, A0.y, B0.x));
            u64 z1 = fma2(s2, A1.x, fma2(a2, A1.y, B1.x));
            u64 z2 = fma2(s2, A2.x, fma2(a2, A2.y, B2.x));
            u64 z3 = fma2(s2, A3.x, fma2(a2, A3.y, B3.x));
            acc0 = add2(acc0, abso2(z0, (unsigned)B0.y, (unsigned)(B0.y >> 32)));
            acc1 = add2(acc1, abso2(z1, (unsigned)B1.y, (unsigned)(B1.y >> 32)));
            acc2 = add2(acc2, abso2(z2, (unsigned)B2.y, (unsigned)(B2.y >> 32)));
            acc3 = add2(acc3, abso2(z3, (unsigned)B3.y, (unsigned)(B3.y >> 32)));
        }
        u64 f = add2(add2(acc0, acc1), add2(acc2, acc3));
        f = add2(f, fma2(s2, g_nlpq, fma2(a2, g_nlr, g_nlb)));
        float f0, f1; unpack2(f, f0, f1);
        float e0 = ex2f(f0), e1 = ex2f(f1);
        float4 ac = g_accum[ii];
        s_S[tid] = make_float2((ac.y + e0 * s) / (ac.x + e0),
                               (ac.w + e1 * s) / (ac.z + e1));
    }
    __syncthreads();

    // phase 2: warp streams 32 nodes, math in f32x2.
    // Row = 128 floats = 512 bytes = 32 ulonglong2 -> stride 32 (R9 bug: was 16).
    int lane = tid & 31, w = tid >> 5;
    ulonglong2 A0v = ((const ulonglong2*)g_A0)[lane];
    ulonglong2 A1v = ((const ulonglong2*)g_A1)[lane];
    ulonglong2 Cv  = ((const ulonglong2*)g_Cv)[lane];
    int base = blockIdx.x * 256 + w * 32;
    ulonglong2* o2p = (ulonglong2*)out;
#pragma unroll 4
    for (int j = 0; j < 32; j++) {
        int node = base + j;
        if (node >= n) break;
        float2 sS = s_S[w * 32 + j];
        u64 sx2 = pack2(sS.x, sS.x), sy2 = pack2(sS.y, sS.y);
        ulonglong2 o;
        o.x = fma2(sx2, A0v.x, fma2(sy2, A1v.x, Cv.x));
        o.y = fma2(sx2, A0v.y, fma2(sy2, A1v.y, Cv.y));
        o2p[(long long)node * 32 + lane] = o;
    }
}

// ---------------------------------------------------------------------------
extern "C" void kernel_launch(void* const* d_in, const int* in_sizes, int n_in,
                              void* d_out, int out_size)
{
    const float* x     = (const float*)d_in[0];
    const void*  eidx  = d_in[1];
    const float* eattr = (const float*)d_in[2];
    const int*   tgtp  = (const int*)d_in[3];
    const float* Wl    = (const float*)d_in[4];
    const float* bl    = (const float*)d_in[5];
    const float* Wr    = (const float*)d_in[6];
    const float* br    = (const float*)d_in[7];
    const float* We    = (const float*)d_in[8];
    const float* att   = (const float*)d_in[9];
    const float* bout  = (const float*)d_in[10];
    const float* Wfc   = (const float*)d_in[11];
    const float* bfc   = (const float*)d_in[12];

    int n = in_sizes[0];   // N nodes (x is [N,1])
    int E = in_sizes[2];   // edges (edge_attr is [E,1])
    float* out = (float*)d_out;

    int nblk = (n + 255) / 256;
    k_zero<<<nblk, 256>>>(n);                                    // idx 0
    k_wprep<<<1, 128>>>(eidx, n, Wl, bl, Wr, br, We, att);       // idx 1
    k_vecA<<<16, 256>>>(Wl, bl, bout, Wfc, bfc);                 // idx 2
    int ethreads = (E + EPT - 1) / EPT;
    k_edges<<<(ethreads + 255) / 256, 256>>>(x, eidx, eattr, E); // idx 3 (profiled)
    k_tgt<<<1, 128>>>(x, tgtp);                                  // idx 4
    k_nodes_out<<<nblk, 256>>>(x, n, out);                       // idx 5
}

// round 11
// speedup vs baseline: 1.0664x; 1.0186x over previous
#include <cuda_runtime.h>

// ---------------------------------------------------------------------------
// GATv2 (H=2, EMB=64) + fused final linear, collapsed to scalar-per-edge form.
// R11: EPT=6 + launch_bounds(256,3) — amortize weight-LDS crossbar bytes over
//      more edges (R10 showed L1/smem crossbar, not occupancy, binds issue).
//      nodes_out keeps the corrected stride + f32x2 phase 2.
//
// Per-edge:  logit_h = 0.6*L_h + 0.4*sum_c att_hc*|z_hc|   (LeakyReLU split)
//            z_hc = s*Wl + t*Wr + a*We + b,  L_h = s*P_h + t*Q_h + a*R_h + B_h
// Per-node:  S_ih = sum_e alpha_eh * x[src_e]   (softmax without max-shift)
// Output:    out[i,:] = S_i0*A0 + S_i1*A1 + (CB + T0*D0 + T1*D1)
// ---------------------------------------------------------------------------

#define NODE_CAP 131072
#define EPT 6

typedef unsigned long long u64;

__device__ float4 g_accum[NODE_CAP];    // {den0, num0, den1, num1}
__device__ float2 g_degattr[NODE_CAP];  // {deg, attr_sum}

// --- edge weights, head-packed f32x2 (lo=head0, hi=head1), natural order
__device__ ulonglong2 g_eA[64];   // {wl2, wr2}
__device__ ulonglong2 g_eB[64];   // {we2, b2}
__device__ u64 g_em[64];          // per-half sign masks of att
__device__ u64 g_lin[4];          // P, Q, R, B head-packed

// --- node (self-loop) weights, head-packed, natural order
__device__ ulonglong2 g_nA[64];   // {wlr2, we2}
__device__ ulonglong2 g_nB[64];   // {b2, m2}
__device__ u64 g_nlpq, g_nlr, g_nlb;

// --- final linear vectors
__device__ __align__(16) float g_A0[128];
__device__ __align__(16) float g_A1[128];
__device__ __align__(16) float g_CB[128];
__device__ __align__(16) float g_D0[128];
__device__ __align__(16) float g_D1[128];
__device__ __align__(16) float g_Cv[128];   // CB + T0*D0 + T1*D1 (k_tgt)
__device__ int g_idx64;

// ---- f32x2 helpers ----
__device__ __forceinline__ u64 pack2(float lo, float hi) {
    u64 r;
    asm("mov.b64 %0, {%1, %2};" : "=l"(r) : "r"(__float_as_uint(lo)), "r"(__float_as_uint(hi)));
    return r;
}
__device__ __forceinline__ void unpack2(u64 v, float& lo, float& hi) {
    unsigned a, b;
    asm("mov.b64 {%0, %1}, %2;" : "=r"(a), "=r"(b) : "l"(v));
    lo = __uint_as_float(a); hi = __uint_as_float(b);
}
__device__ __forceinline__ u64 fma2(u64 a, u64 b, u64 c) {
    u64 d;
    asm("fma.rn.f32x2 %0, %1, %2, %3;" : "=l"(d) : "l"(a), "l"(b), "l"(c));
    return d;
}
__device__ __forceinline__ u64 add2(u64 a, u64 b) {
    u64 d;
    asm("add.rn.f32x2 %0, %1, %2;" : "=l"(d) : "l"(a), "l"(b));
    return d;
}
// per 32-bit half: (z & 0x7fffffff) | mask   (LOP3, immLut 0xEA)
__device__ __forceinline__ u64 abso2(u64 z, unsigned mlo, unsigned mhi) {
    unsigned lo, hi, rlo, rhi;
    asm("mov.b64 {%0, %1}, %2;" : "=r"(lo), "=r"(hi) : "l"(z));
    asm("lop3.b32 %0, %1, 0x7fffffff, %2, 0xEA;" : "=r"(rlo) : "r"(lo), "r"(mlo));
    asm("lop3.b32 %0, %1, 0x7fffffff, %2, 0xEA;" : "=r"(rhi) : "r"(hi), "r"(mhi));
    u64 r;
    asm("mov.b64 %0, {%1, %2};" : "=l"(r) : "r"(rlo), "r"(rhi));
    return r;
}
__device__ __forceinline__ float ex2f(float x) {
    float r;
    asm("ex2.approx.f32 %0, %1;" : "=f"(r) : "f"(x));
    return r;
}

// ---------------------------------------------------------------------------
// launch 0: zero accumulators
__global__ void __launch_bounds__(256) k_zero(int n)
{
    int i = blockIdx.x * blockDim.x + threadIdx.x;
    if (i < n) {
        g_accum[i] = make_float4(0.f, 0.f, 0.f, 0.f);
        g_degattr[i] = make_float2(0.f, 0.f);
    }
}

// ---------------------------------------------------------------------------
// launch 1: weight prep (1 block, 128 threads)
__global__ void k_wprep(const void* __restrict__ eidx, int n,
                        const float* __restrict__ Wl, const float* __restrict__ bl,
                        const float* __restrict__ Wr, const float* __restrict__ br,
                        const float* __restrict__ We, const float* __restrict__ att)
{
    const float LOG2E = 1.4426950408889634f;
    const float kap = 0.4f * LOG2E;
    const float lam = 0.6f * LOG2E;
    int tid = threadIdx.x;
    if (tid < 64) {
        int c = tid;
        float a0 = att[c], a1 = att[64 + c];
        float k0 = kap * a0, k1 = kap * a1;
        float wl0 = k0 * Wl[c], wl1 = k1 * Wl[64 + c];
        float wr0 = k0 * Wr[c], wr1 = k1 * Wr[64 + c];
        float we0 = k0 * We[c], we1 = k1 * We[64 + c];
        float b0 = k0 * (bl[c] + br[c]), b1 = k1 * (bl[64 + c] + br[64 + c]);
        unsigned m0 = __float_as_uint(a0) & 0x80000000u;
        unsigned m1 = __float_as_uint(a1) & 0x80000000u;
        u64 m2 = ((u64)m1 << 32) | (u64)m0;
        ulonglong2 eA; eA.x = pack2(wl0, wl1); eA.y = pack2(wr0, wr1);
        ulonglong2 eB; eB.x = pack2(we0, we1); eB.y = pack2(b0, b1);
        g_eA[c] = eA; g_eB[c] = eB; g_em[c] = m2;
        ulonglong2 nA; nA.x = pack2(wl0 + wr0, wl1 + wr1); nA.y = eB.x;
        ulonglong2 nB; nB.x = eB.y; nB.y = m2;
        g_nA[c] = nA; g_nB[c] = nB;
    }
    if (tid == 0) {
        float Ph[2], Qh[2], Rh[2], Bh[2];
        for (int h = 0; h < 2; h++) {
            float P = 0, Q = 0, R = 0, B = 0;
            for (int c = 0; c < 64; c++) {
                int j = h * 64 + c;
                float aA = att[j];
                P += aA * Wl[j]; Q += aA * Wr[j]; R += aA * We[j];
                B += aA * (bl[j] + br[j]);
            }
            Ph[h] = lam * P; Qh[h] = lam * Q; Rh[h] = lam * R; Bh[h] = lam * B;
        }
        g_lin[0] = pack2(Ph[0], Ph[1]);
        g_lin[1] = pack2(Qh[0], Qh[1]);
        g_lin[2] = pack2(Rh[0], Rh[1]);
        g_lin[3] = pack2(Bh[0], Bh[1]);
        g_nlpq = pack2(Ph[0] + Qh[0], Ph[1] + Qh[1]);
        g_nlr  = g_lin[2];
        g_nlb  = g_lin[3];
        // edge_index dtype detection (int64 values all < n)
        const u64* p = (const u64*)eidx;
        int is64 = 1;
        for (int k = 0; k < 16; k++)
            if (p[k] >= (u64)n) is64 = 0;
        g_idx64 = is64;
    }
}

// ---------------------------------------------------------------------------
// launch 2: final-linear vectors (weights-only). Warp per output row.
__global__ void __launch_bounds__(256) k_vecA(
    const float* __restrict__ Wl, const float* __restrict__ bl,
    const float* __restrict__ bout, const float* __restrict__ Wfc,
    const float* __restrict__ bfc)
{
    int lane = threadIdx.x & 31;
    int j = (blockIdx.x * blockDim.x + threadIdx.x) >> 5;
    if (j >= 128) return;
    const float* wrow = Wfc + j * 256;

    float a0 = 0.f, a1 = 0.f, cb = 0.f, d0 = 0.f, d1 = 0.f;
#pragma unroll
    for (int u = 0; u < 8; u++) {
        int idx = u * 32 + lane;
        float w = wrow[idx];
        if (u < 2) {
            a0 += Wl[idx] * w;
            cb += (bl[idx] + bout[idx]) * w;
        } else if (u < 4) {
            a1 += Wl[idx] * w;
            cb += (bl[idx] + bout[idx]) * w;
        } else if (u < 6) {
            int kk = idx - 128;
            cb += (bl[kk] + bout[kk]) * w;
            d0 += Wl[kk] * w;
        } else {
            int kk = idx - 128;
            cb += (bl[kk] + bout[kk]) * w;
            d1 += Wl[kk] * w;
        }
    }
#pragma unroll
    for (int off = 16; off > 0; off >>= 1) {
        a0 += __shfl_xor_sync(0xffffffffu, a0, off);
        a1 += __shfl_xor_sync(0xffffffffu, a1, off);
        cb += __shfl_xor_sync(0xffffffffu, cb, off);
        d0 += __shfl_xor_sync(0xffffffffu, d0, off);
        d1 += __shfl_xor_sync(0xffffffffu, d1, off);
    }
    if (lane == 0) {
        g_A0[j] = a0; g_A1[j] = a1; g_CB[j] = cb + bfc[j];
        g_D0[j] = d0; g_D1[j] = d1;
    }
}

// ---------------------------------------------------------------------------
// launch 3 (PROFILED): edge pass.  EPT=6, 3 CTAs/SM (~85 reg leash).
__global__ void __launch_bounds__(256, 3) k_edges(
    const float* __restrict__ x, const void* __restrict__ eidx,
    const float* __restrict__ eattr, int E)
{
    __shared__ ulonglong2 s_eA[64], s_eB[64];
    __shared__ u64 s_m[64];
    int tid = threadIdx.x;
    if (tid < 64) { s_eA[tid] = g_eA[tid]; s_eB[tid] = g_eB[tid]; s_m[tid] = g_em[tid]; }
    __syncthreads();

    long long base = (long long)(blockIdx.x * blockDim.x + tid) * EPT;
    if (base >= E) return;
    int idx64 = g_idx64;
    const long long* p64 = (const long long*)eidx;
    const int* p32 = (const int*)eidx;

    u64 s2[EPT], t2[EPT], a2[EPT], acc[EPT];
    int dsti[EPT];

#pragma unroll
    for (int k = 0; k < EPT; k++) {
        long long e = base + k; if (e > E - 1) e = E - 1;
        int si, di;
        if (idx64) { si = (int)p64[e]; di = (int)p64[E + e]; }
        else       { si = p32[e];      di = p32[E + e]; }
        dsti[k] = di;
        float aa = eattr[e];
        float s = x[si], t = x[di];
        s2[k] = pack2(s, s); t2[k] = pack2(t, t); a2[k] = pack2(aa, aa);
        acc[k] = 0ull;
    }

#pragma unroll 4
    for (int c = 0; c < 64; c++) {
        ulonglong2 wA = s_eA[c];   // {wl, wr}
        ulonglong2 wB = s_eB[c];   // {we, b}
        u64 mm = s_m[c];
        unsigned mlo = (unsigned)mm, mhi = (unsigned)(mm >> 32);
#pragma unroll
        for (int k = 0; k < EPT; k++) {
            u64 z = fma2(a2[k], wB.x, wB.y);
            z = fma2(t2[k], wA.y, z);
            z = fma2(s2[k], wA.x, z);
            acc[k] = add2(acc[k], abso2(z, mlo, mhi));
        }
    }

    u64 P = g_lin[0], Q = g_lin[1], R = g_lin[2], B = g_lin[3];
#pragma unroll
    for (int k = 0; k < EPT; k++) {
        if (base + k >= E) continue;
        u64 f2 = add2(acc[k], B);
        f2 = fma2(a2[k], R, f2);
        f2 = fma2(t2[k], Q, f2);
        f2 = fma2(s2[k], P, f2);
        float f0, f1; unpack2(f2, f0, f1);
        float e0 = ex2f(f0), e1 = ex2f(f1);
        float sv, av, dum;
        unpack2(s2[k], sv, dum);
        unpack2(a2[k], av, dum);
        atomicAdd(&g_degattr[dsti[k]], make_float2(1.0f, av));
        atomicAdd(&g_accum[dsti[k]], make_float4(e0, e0 * sv, e1, e1 * sv));
    }
}

// ---------------------------------------------------------------------------
// launch 4: S[target] + folded constant vector Cv (1 block, 128 threads)
__global__ void k_tgt(const float* __restrict__ x, const int* __restrict__ tgtp)
{
    __shared__ float2 sh_S;
    int tid = threadIdx.x;
    int tgt = tgtp[0];   // low 32 bits valid for int32/int64 (LE)
    if (tid < 32) {
        float s = x[tgt];
        float2 da = g_degattr[tgt];
        float am = da.y / fmaxf(da.x, 1.0f);
        u64 s2 = pack2(s, s), a2 = pack2(am, am);
        u64 acc = 0ull;
        for (int c = tid; c < 64; c += 32) {
            ulonglong2 A = g_nA[c], Bv = g_nB[c];
            u64 z = fma2(a2, A.y, Bv.x);
            z = fma2(s2, A.x, z);
            acc = add2(acc, abso2(z, (unsigned)Bv.y, (unsigned)(Bv.y >> 32)));
        }
        float h0, h1; unpack2(acc, h0, h1);
#pragma unroll
        for (int off = 16; off > 0; off >>= 1) {
            h0 += __shfl_xor_sync(0xffffffffu, h0, off);
            h1 += __shfl_xor_sync(0xffffffffu, h1, off);
        }
        u64 f = add2(pack2(h0, h1), fma2(s2, g_nlpq, fma2(a2, g_nlr, g_nlb)));
        float f0, f1; unpack2(f, f0, f1);
        float e0 = ex2f(f0), e1 = ex2f(f1);
        float4 ac = g_accum[tgt];
        if (tid == 0)
            sh_S = make_float2((ac.y + e0 * s) / (ac.x + e0),
                               (ac.w + e1 * s) / (ac.z + e1));
    }
    __syncthreads();
    float2 st = sh_S;
    if (tid < 128)
        g_Cv[tid] = fmaf(st.x, g_D0[tid], fmaf(st.y, g_D1[tid], g_CB[tid]));
}

// ---------------------------------------------------------------------------
// launch 5: fused self-loop/softmax finalize + output write (f32x2 phase 2).
__global__ void __launch_bounds__(256) k_nodes_out(
    const float* __restrict__ x, int n, float* __restrict__ out)
{
    __shared__ ulonglong2 s_A[64], s_B[64];
    __shared__ float2 s_S[256];
    int tid = threadIdx.x;
    if (tid < 64) { s_A[tid] = g_nA[tid]; s_B[tid] = g_nB[tid]; }
    __syncthreads();

    int i = blockIdx.x * 256 + tid;
    int ii = (i < n) ? i : (n - 1);
    {
        float s = x[ii];
        float2 da = g_degattr[ii];
        float am = da.y / fmaxf(da.x, 1.0f);
        u64 s2 = pack2(s, s), a2 = pack2(am, am);
        u64 acc0 = 0ull, acc1 = 0ull, acc2 = 0ull, acc3 = 0ull;
#pragma unroll 2
        for (int c = 0; c < 64; c += 4) {
            ulonglong2 A0 = s_A[c],     B0 = s_B[c];
            ulonglong2 A1 = s_A[c + 1], B1 = s_B[c + 1];
            ulonglong2 A2 = s_A[c + 2], B2 = s_B[c + 2];
            ulonglong2 A3 = s_A[c + 3], B3 = s_B[c + 3];
            u64 z0 = fma2(s2, A0.x, fma2(a2, A0.y, B0.x));
            u64 z1 = fma2(s2, A1.x, fma2(a2, A1.y, B1.x));
            u64 z2 = fma2(s2, A2.x, fma2(a2, A2.y, B2.x));
            u64 z3 = fma2(s2, A3.x, fma2(a2, A3.y, B3.x));
            acc0 = add2(acc0, abso2(z0, (unsigned)B0.y, (unsigned)(B0.y >> 32)));
            acc1 = add2(acc1, abso2(z1, (unsigned)B1.y, (unsigned)(B1.y >> 32)));
            acc2 = add2(acc2, abso2(z2, (unsigned)B2.y, (unsigned)(B2.y >> 32)));
            acc3 = add2(acc3, abso2(z3, (unsigned)B3.y, (unsigned)(B3.y >> 32)));
        }
        u64 f = add2(add2(acc0, acc1), add2(acc2, acc3));
        f = add2(f, fma2(s2, g_nlpq, fma2(a2, g_nlr, g_nlb)));
        float f0, f1; unpack2(f, f0, f1);
        float e0 = ex2f(f0), e1 = ex2f(f1);
        float4 ac = g_accum[ii];
        s_S[tid] = make_float2((ac.y + e0 * s) / (ac.x + e0),
                               (ac.w + e1 * s) / (ac.z + e1));
    }
    __syncthreads();

    // phase 2: warp streams 32 nodes, math in f32x2.
    // Row = 128 floats = 512 bytes = 32 ulonglong2 -> stride 32.
    int lane = tid & 31, w = tid >> 5;
    ulonglong2 A0v = ((const ulonglong2*)g_A0)[lane];
    ulonglong2 A1v = ((const ulonglong2*)g_A1)[lane];
    ulonglong2 Cv  = ((const ulonglong2*)g_Cv)[lane];
    int base = blockIdx.x * 256 + w * 32;
    ulonglong2* o2p = (ulonglong2*)out;
#pragma unroll 4
    for (int j = 0; j < 32; j++) {
        int node = base + j;
        if (node >= n) break;
        float2 sS = s_S[w * 32 + j];
        u64 sx2 = pack2(sS.x, sS.x), sy2 = pack2(sS.y, sS.y);
        ulonglong2 o;
        o.x = fma2(sx2, A0v.x, fma2(sy2, A1v.x, Cv.x));
        o.y = fma2(sx2, A0v.y, fma2(sy2, A1v.y, Cv.y));
        o2p[(long long)node * 32 + lane] = o;
    }
}

// ---------------------------------------------------------------------------
extern "C" void kernel_launch(void* const* d_in, const int* in_sizes, int n_in,
                              void* d_out, int out_size)
{
    const float* x     = (const float*)d_in[0];
    const void*  eidx  = d_in[1];
    const float* eattr = (const float*)d_in[2];
    const int*   tgtp  = (const int*)d_in[3];
    const float* Wl    = (const float*)d_in[4];
    const float* bl    = (const float*)d_in[5];
    const float* Wr    = (const float*)d_in[6];
    const float* br    = (const float*)d_in[7];
    const float* We    = (const float*)d_in[8];
    const float* att   = (const float*)d_in[9];
    const float* bout  = (const float*)d_in[10];
    const float* Wfc   = (const float*)d_in[11];
    const float* bfc   = (const float*)d_in[12];

    int n = in_sizes[0];   // N nodes (x is [N,1])
    int E = in_sizes[2];   // edges (edge_attr is [E,1])
    float* out = (float*)d_out;

    int nblk = (n + 255) / 256;
    k_zero<<<nblk, 256>>>(n);                                    // idx 0
    k_wprep<<<1, 128>>>(eidx, n, Wl, bl, Wr, br, We, att);       // idx 1
    k_vecA<<<16, 256>>>(Wl, bl, bout, Wfc, bfc);                 // idx 2
    long long ethreads = ((long long)E + EPT - 1) / EPT;
    k_edges<<<(int)((ethreads + 255) / 256), 256>>>(x, eidx, eattr, E); // idx 3 (profiled)
    k_tgt<<<1, 128>>>(x, tgtp);                                  // idx 4
    k_nodes_out<<<nblk, 256>>>(x, n, out);                       // idx 5
}

// round 12
// speedup vs baseline: 1.2186x; 1.1428x over previous
#include <cuda_runtime.h>

// ---------------------------------------------------------------------------
// GATv2 (H=2, EMB=64) + fused final linear, collapsed to scalar-per-edge form.
// R12: edges = R7-exact (EPT=4, proven 52.3us ~ FMA2-pipe floor: rt(FFMA2)=4).
//      Merged setup kernel (zero+wprep+vecA). nodes_out: accum prefetch,
//      4 acc chains, f32x2 phase 2, fast path for full blocks.
//
// Per-edge:  logit_h = 0.6*L_h + 0.4*sum_c att_hc*|z_hc|   (LeakyReLU split)
//            z_hc = s*Wl + t*Wr + a*We + b,  L_h = s*P_h + t*Q_h + a*R_h + B_h
// Per-node:  S_ih = sum_e alpha_eh * x[src_e]   (softmax without max-shift)
// Output:    out[i,:] = S_i0*A0 + S_i1*A1 + (CB + T0*D0 + T1*D1)
// ---------------------------------------------------------------------------

#define NODE_CAP 131072
#define EPT 4

typedef unsigned long long u64;

__device__ float4 g_accum[NODE_CAP];    // {den0, num0, den1, num1}
__device__ float2 g_degattr[NODE_CAP];  // {deg, attr_sum}

// --- edge weights, head-packed f32x2 (lo=head0, hi=head1), natural order
__device__ ulonglong2 g_eA[64];   // {wl2, wr2}
__device__ ulonglong2 g_eB[64];   // {we2, b2}
__device__ u64 g_em[64];          // per-half sign masks of att
__device__ u64 g_lin[4];          // P, Q, R, B head-packed

// --- node (self-loop) weights, head-packed, natural order
__device__ ulonglong2 g_nA[64];   // {wlr2, we2}
__device__ ulonglong2 g_nB[64];   // {b2, m2}
__device__ u64 g_nlpq, g_nlr, g_nlb;

// --- final linear vectors
__device__ __align__(16) float g_A0[128];
__device__ __align__(16) float g_A1[128];
__device__ __align__(16) float g_CB[128];
__device__ __align__(16) float g_D0[128];
__device__ __align__(16) float g_D1[128];
__device__ __align__(16) float g_Cv[128];   // CB + T0*D0 + T1*D1 (k_tgt)
__device__ int g_idx64;

// ---- f32x2 helpers ----
__device__ __forceinline__ u64 pack2(float lo, float hi) {
    u64 r;
    asm("mov.b64 %0, {%1, %2};" : "=l"(r) : "r"(__float_as_uint(lo)), "r"(__float_as_uint(hi)));
    return r;
}
__device__ __forceinline__ void unpack2(u64 v, float& lo, float& hi) {
    unsigned a, b;
    asm("mov.b64 {%0, %1}, %2;" : "=r"(a), "=r"(b) : "l"(v));
    lo = __uint_as_float(a); hi = __uint_as_float(b);
}
__device__ __forceinline__ u64 fma2(u64 a, u64 b, u64 c) {
    u64 d;
    asm("fma.rn.f32x2 %0, %1, %2, %3;" : "=l"(d) : "l"(a), "l"(b), "l"(c));
    return d;
}
__device__ __forceinline__ u64 add2(u64 a, u64 b) {
    u64 d;
    asm("add.rn.f32x2 %0, %1, %2;" : "=l"(d) : "l"(a), "l"(b));
    return d;
}
// per 32-bit half: (z & 0x7fffffff) | mask   (LOP3, immLut 0xEA)
__device__ __forceinline__ u64 abso2(u64 z, unsigned mlo, unsigned mhi) {
    unsigned lo, hi, rlo, rhi;
    asm("mov.b64 {%0, %1}, %2;" : "=r"(lo), "=r"(hi) : "l"(z));
    asm("lop3.b32 %0, %1, 0x7fffffff, %2, 0xEA;" : "=r"(rlo) : "r"(lo), "r"(mlo));
    asm("lop3.b32 %0, %1, 0x7fffffff, %2, 0xEA;" : "=r"(rhi) : "r"(hi), "r"(mhi));
    u64 r;
    asm("mov.b64 %0, {%1, %2};" : "=l"(r) : "r"(rlo), "r"(rhi));
    return r;
}
__device__ __forceinline__ float ex2f(float x) {
    float r;
    asm("ex2.approx.f32 %0, %1;" : "=f"(r) : "f"(x));
    return r;
}

// ---------------------------------------------------------------------------
// launch 0: merged setup.
//   block 0:        weight prep (edge arrays, node arrays, lin, dtype detect)
//   blocks 1..16:   final-linear vectors (warp per output row)
//   blocks 17+:     zero node accumulators
__global__ void __launch_bounds__(256) k_setup(
    const void* __restrict__ eidx, int n,
    const float* __restrict__ Wl, const float* __restrict__ bl,
    const float* __restrict__ Wr, const float* __restrict__ br,
    const float* __restrict__ We, const float* __restrict__ att,
    const float* __restrict__ bout, const float* __restrict__ Wfc,
    const float* __restrict__ bfc)
{
    const float LOG2E = 1.4426950408889634f;
    const float kap = 0.4f * LOG2E;
    const float lam = 0.6f * LOG2E;
    int bid = blockIdx.x;
    int tid = threadIdx.x;

    if (bid >= 17) {                 // zeroing
        int i = (bid - 17) * 256 + tid;
        if (i < n) {
            g_accum[i] = make_float4(0.f, 0.f, 0.f, 0.f);
            g_degattr[i] = make_float2(0.f, 0.f);
        }
        return;
    }
    if (bid >= 1) {                  // vecA: warp per output row j
        int lane = tid & 31;
        int j = (bid - 1) * 8 + (tid >> 5);
        const float* wrow = Wfc + j * 256;
        float a0 = 0.f, a1 = 0.f, cb = 0.f, d0 = 0.f, d1 = 0.f;
#pragma unroll
        for (int u = 0; u < 8; u++) {
            int idx = u * 32 + lane;
            float w = wrow[idx];
            if (u < 2) {
                a0 += Wl[idx] * w;
                cb += (bl[idx] + bout[idx]) * w;
            } else if (u < 4) {
                a1 += Wl[idx] * w;
                cb += (bl[idx] + bout[idx]) * w;
            } else if (u < 6) {
                int kk = idx - 128;
                cb += (bl[kk] + bout[kk]) * w;
                d0 += Wl[kk] * w;
            } else {
                int kk = idx - 128;
                cb += (bl[kk] + bout[kk]) * w;
                d1 += Wl[kk] * w;
            }
        }
#pragma unroll
        for (int off = 16; off > 0; off >>= 1) {
            a0 += __shfl_xor_sync(0xffffffffu, a0, off);
            a1 += __shfl_xor_sync(0xffffffffu, a1, off);
            cb += __shfl_xor_sync(0xffffffffu, cb, off);
            d0 += __shfl_xor_sync(0xffffffffu, d0, off);
            d1 += __shfl_xor_sync(0xffffffffu, d1, off);
        }
        if (lane == 0) {
            g_A0[j] = a0; g_A1[j] = a1; g_CB[j] = cb + bfc[j];
            g_D0[j] = d0; g_D1[j] = d1;
        }
        return;
    }

    // block 0: weight prep
    if (tid < 64) {
        int c = tid;
        float a0 = att[c], a1 = att[64 + c];
        float k0 = kap * a0, k1 = kap * a1;
        float wl0 = k0 * Wl[c], wl1 = k1 * Wl[64 + c];
        float wr0 = k0 * Wr[c], wr1 = k1 * Wr[64 + c];
        float we0 = k0 * We[c], we1 = k1 * We[64 + c];
        float b0 = k0 * (bl[c] + br[c]), b1 = k1 * (bl[64 + c] + br[64 + c]);
        unsigned m0 = __float_as_uint(a0) & 0x80000000u;
        unsigned m1 = __float_as_uint(a1) & 0x80000000u;
        u64 m2 = ((u64)m1 << 32) | (u64)m0;
        ulonglong2 eA; eA.x = pack2(wl0, wl1); eA.y = pack2(wr0, wr1);
        ulonglong2 eB; eB.x = pack2(we0, we1); eB.y = pack2(b0, b1);
        g_eA[c] = eA; g_eB[c] = eB; g_em[c] = m2;
        ulonglong2 nA; nA.x = pack2(wl0 + wr0, wl1 + wr1); nA.y = eB.x;
        ulonglong2 nB; nB.x = eB.y; nB.y = m2;
        g_nA[c] = nA; g_nB[c] = nB;
    }
    if (tid == 0) {
        float Ph[2], Qh[2], Rh[2], Bh[2];
        for (int h = 0; h < 2; h++) {
            float P = 0, Q = 0, R = 0, B = 0;
            for (int c = 0; c < 64; c++) {
                int j = h * 64 + c;
                float aA = att[j];
                P += aA * Wl[j]; Q += aA * Wr[j]; R += aA * We[j];
                B += aA * (bl[j] + br[j]);
            }
            Ph[h] = lam * P; Qh[h] = lam * Q; Rh[h] = lam * R; Bh[h] = lam * B;
        }
        g_lin[0] = pack2(Ph[0], Ph[1]);
        g_lin[1] = pack2(Qh[0], Qh[1]);
        g_lin[2] = pack2(Rh[0], Rh[1]);
        g_lin[3] = pack2(Bh[0], Bh[1]);
        g_nlpq = pack2(Ph[0] + Qh[0], Ph[1] + Qh[1]);
        g_nlr  = g_lin[2];
        g_nlb  = g_lin[3];
        // edge_index dtype detection (int64 values all < n)
        const u64* p = (const u64*)eidx;
        int is64 = 1;
        for (int k = 0; k < 16; k++)
            if (p[k] >= (u64)n) is64 = 0;
        g_idx64 = is64;
    }
}

// ---------------------------------------------------------------------------
// launch 1: edge pass (R7-exact: EPT=4, at the FFMA2-pipe floor)
__global__ void __launch_bounds__(256, 2) k_edges(
    const float* __restrict__ x, const void* __restrict__ eidx,
    const float* __restrict__ eattr, int E)
{
    __shared__ ulonglong2 s_eA[64], s_eB[64];
    __shared__ u64 s_m[64];
    int tid = threadIdx.x;
    if (tid < 64) { s_eA[tid] = g_eA[tid]; s_eB[tid] = g_eB[tid]; s_m[tid] = g_em[tid]; }
    __syncthreads();

    int base = (blockIdx.x * blockDim.x + tid) * EPT;
    if (base >= E) return;
    int idx64 = g_idx64;
    const long long* p64 = (const long long*)eidx;
    const int* p32 = (const int*)eidx;

    u64 s2[EPT], t2[EPT], a2[EPT], acc[EPT];
    int dsti[EPT];

#pragma unroll
    for (int k = 0; k < EPT; k++) {
        int e = base + k; if (e > E - 1) e = E - 1;
        int si, di;
        if (idx64) { si = (int)p64[e]; di = (int)p64[E + e]; }
        else       { si = p32[e];      di = p32[E + e]; }
        dsti[k] = di;
        float aa = eattr[e];
        float s = x[si], t = x[di];
        s2[k] = pack2(s, s); t2[k] = pack2(t, t); a2[k] = pack2(aa, aa);
        acc[k] = 0ull;
    }

#pragma unroll 8
    for (int c = 0; c < 64; c++) {
        ulonglong2 wA = s_eA[c];   // {wl, wr}
        ulonglong2 wB = s_eB[c];   // {we, b}
        u64 mm = s_m[c];
        unsigned mlo = (unsigned)mm, mhi = (unsigned)(mm >> 32);
#pragma unroll
        for (int k = 0; k < EPT; k++) {
            u64 z = fma2(a2[k], wB.x, wB.y);
            z = fma2(t2[k], wA.y, z);
            z = fma2(s2[k], wA.x, z);
            acc[k] = add2(acc[k], abso2(z, mlo, mhi));
        }
    }

    u64 P = g_lin[0], Q = g_lin[1], R = g_lin[2], B = g_lin[3];
#pragma unroll
    for (int k = 0; k < EPT; k++) {
        if (base + k >= E) continue;
        u64 f2 = add2(acc[k], B);
        f2 = fma2(a2[k], R, f2);
        f2 = fma2(t2[k], Q, f2);
        f2 = fma2(s2[k], P, f2);
        float f0, f1; unpack2(f2, f0, f1);
        float e0 = ex2f(f0), e1 = ex2f(f1);
        float sv, av, dum;
        unpack2(s2[k], sv, dum);
        unpack2(a2[k], av, dum);
        atomicAdd(&g_degattr[dsti[k]], make_float2(1.0f, av));
        atomicAdd(&g_accum[dsti[k]], make_float4(e0, e0 * sv, e1, e1 * sv));
    }
}

// ---------------------------------------------------------------------------
// launch 2: S[target] + folded constant vector Cv (1 block, 128 threads)
__global__ void k_tgt(const float* __restrict__ x, const int* __restrict__ tgtp)
{
    __shared__ float2 sh_S;
    int tid = threadIdx.x;
    int tgt = tgtp[0];   // low 32 bits valid for int32/int64 (LE)
    if (tid < 32) {
        float s = x[tgt];
        float2 da = g_degattr[tgt];
        float am = da.y / fmaxf(da.x, 1.0f);
        u64 s2 = pack2(s, s), a2 = pack2(am, am);
        u64 acc = 0ull;
        for (int c = tid; c < 64; c += 32) {
            ulonglong2 A = g_nA[c], Bv = g_nB[c];
            u64 z = fma2(a2, A.y, Bv.x);
            z = fma2(s2, A.x, z);
            acc = add2(acc, abso2(z, (unsigned)Bv.y, (unsigned)(Bv.y >> 32)));
        }
        float h0, h1; unpack2(acc, h0, h1);
#pragma unroll
        for (int off = 16; off > 0; off >>= 1) {
            h0 += __shfl_xor_sync(0xffffffffu, h0, off);
            h1 += __shfl_xor_sync(0xffffffffu, h1, off);
        }
        u64 f = add2(pack2(h0, h1), fma2(s2, g_nlpq, fma2(a2, g_nlr, g_nlb)));
        float f0, f1; unpack2(f, f0, f1);
        float e0 = ex2f(f0), e1 = ex2f(f1);
        float4 ac = g_accum[tgt];
        if (tid == 0)
            sh_S = make_float2((ac.y + e0 * s) / (ac.x + e0),
                               (ac.w + e1 * s) / (ac.z + e1));
    }
    __syncthreads();
    float2 st = sh_S;
    if (tid < 128)
        g_Cv[tid] = fmaf(st.x, g_D0[tid], fmaf(st.y, g_D1[tid], g_CB[tid]));
}

// ---------------------------------------------------------------------------
// launch 3 (PROFILED): fused self-loop/softmax finalize + output write.
// Phase 1: thread per node, accum prefetched, 4 acc chains.
// Phase 2: warp streams 32 nodes in f32x2, fast path for full blocks.
__global__ void __launch_bounds__(256) k_nodes_out(
    const float* __restrict__ x, int n, float* __restrict__ out)
{
    __shared__ ulonglong2 s_A[64], s_B[64];
    __shared__ float2 s_S[256];
    int tid = threadIdx.x;
    if (tid < 64) { s_A[tid] = g_nA[tid]; s_B[tid] = g_nB[tid]; }
    __syncthreads();

    int i = blockIdx.x * 256 + tid;
    int ii = (i < n) ? i : (n - 1);
    {
        // independent global loads issued up front (MLP=3)
        float s = x[ii];
        float2 da = g_degattr[ii];
        float4 ac = g_accum[ii];

        float am = da.y / fmaxf(da.x, 1.0f);
        u64 s2 = pack2(s, s), a2 = pack2(am, am);
        u64 acc0 = 0ull, acc1 = 0ull, acc2 = 0ull, acc3 = 0ull;
#pragma unroll 2
        for (int c = 0; c < 64; c += 4) {
            ulonglong2 A0 = s_A[c],     B0 = s_B[c];
            ulonglong2 A1 = s_A[c + 1], B1 = s_B[c + 1];
            ulonglong2 A2 = s_A[c + 2], B2 = s_B[c + 2];
            ulonglong2 A3 = s_A[c + 3], B3 = s_B[c + 3];
            u64 z0 = fma2(s2, A0.x, fma2(a2, A0.y, B0.x));
            u64 z1 = fma2(s2, A1.x, fma2(a2, A1.y, B1.x));
            u64 z2 = fma2(s2, A2.x, fma2(a2, A2.y, B2.x));
            u64 z3 = fma2(s2, A3.x, fma2(a2, A3.y, B3.x));
            acc0 = add2(acc0, abso2(z0, (unsigned)B0.y, (unsigned)(B0.y >> 32)));
            acc1 = add2(acc1, abso2(z1, (unsigned)B1.y, (unsigned)(B1.y >> 32)));
            acc2 = add2(acc2, abso2(z2, (unsigned)B2.y, (unsigned)(B2.y >> 32)));
            acc3 = add2(acc3, abso2(z3, (unsigned)B3.y, (unsigned)(B3.y >> 32)));
        }
        u64 f = add2(add2(acc0, acc1), add2(acc2, acc3));
        f = add2(f, fma2(s2, g_nlpq, fma2(a2, g_nlr, g_nlb)));
        float f0, f1; unpack2(f, f0, f1);
        float e0 = ex2f(f0), e1 = ex2f(f1);
        s_S[tid] = make_float2((ac.y + e0 * s) / (ac.x + e0),
                               (ac.w + e1 * s) / (ac.z + e1));
    }
    __syncthreads();

    // phase 2: warp streams 32 nodes, math in f32x2.
    // Row = 128 floats = 512 bytes = 32 ulonglong2 -> stride 32.
    int lane = tid & 31, w = tid >> 5;
    ulonglong2 A0v = ((const ulonglong2*)g_A0)[lane];
    ulonglong2 A1v = ((const ulonglong2*)g_A1)[lane];
    ulonglong2 Cv  = ((const ulonglong2*)g_Cv)[lane];
    int base = blockIdx.x * 256 + w * 32;
    ulonglong2* o2p = (ulonglong2*)out;
    if (base + 32 <= n) {
#pragma unroll 8
        for (int j = 0; j < 32; j++) {
            float2 sS = s_S[w * 32 + j];
            u64 sx2 = pack2(sS.x, sS.x), sy2 = pack2(sS.y, sS.y);
            ulonglong2 o;
            o.x = fma2(sx2, A0v.x, fma2(sy2, A1v.x, Cv.x));
            o.y = fma2(sx2, A0v.y, fma2(sy2, A1v.y, Cv.y));
            o2p[(long long)(base + j) * 32 + lane] = o;
        }
    } else {
        for (int j = 0; j < 32; j++) {
            int node = base + j;
            if (node >= n) break;
            float2 sS = s_S[w * 32 + j];
            u64 sx2 = pack2(sS.x, sS.x), sy2 = pack2(sS.y, sS.y);
            ulonglong2 o;
            o.x = fma2(sx2, A0v.x, fma2(sy2, A1v.x, Cv.x));
            o.y = fma2(sx2, A0v.y, fma2(sy2, A1v.y, Cv.y));
            o2p[(long long)node * 32 + lane] = o;
        }
    }
}

// ---------------------------------------------------------------------------
extern "C" void kernel_launch(void* const* d_in, const int* in_sizes, int n_in,
                              void* d_out, int out_size)
{
    const float* x     = (const float*)d_in[0];
    const void*  eidx  = d_in[1];
    const float* eattr = (const float*)d_in[2];
    const int*   tgtp  = (const int*)d_in[3];
    const float* Wl    = (const float*)d_in[4];
    const float* bl    = (const float*)d_in[5];
    const float* Wr    = (const float*)d_in[6];
    const float* br    = (const float*)d_in[7];
    const float* We    = (const float*)d_in[8];
    const float* att   = (const float*)d_in[9];
    const float* bout  = (const float*)d_in[10];
    const float* Wfc   = (const float*)d_in[11];
    const float* bfc   = (const float*)d_in[12];

    int n = in_sizes[0];   // N nodes (x is [N,1])
    int E = in_sizes[2];   // edges (edge_attr is [E,1])
    float* out = (float*)d_out;

    int nblk = (n + 255) / 256;
    k_setup<<<nblk + 17, 256>>>(eidx, n, Wl, bl, Wr, br, We, att,
                                bout, Wfc, bfc);                 // idx 0
    int ethreads = (E + EPT - 1) / EPT;
    k_edges<<<(ethreads + 255) / 256, 256>>>(x, eidx, eattr, E); // idx 1
    k_tgt<<<1, 128>>>(x, tgtp);                                  // idx 2
    k_nodes_out<<<nblk, 256>>>(x, n, out);                       // idx 3 (profiled)
}